// round 7
// baseline (speedup 1.0000x reference)
#include <cuda_runtime.h>
#include <cstdint>

#define BATCH       8192
#define FEAT_DIM    2048
#define NUM_CLASSES 751
#define TPB         256
#define NBLK        1184                        // 8 CTAs/SM * 148 SMs, one wave
#define NTHREADS    (NBLK * TPB)                // 303104
#define TOTAL4      (BATCH * (FEAT_DIM / 4))    // 4,194,304 float4 pairs

__device__ float        g_partial[NBLK];
__device__ unsigned int g_done_count;           // zero at load; last block resets

__global__ void __launch_bounds__(TPB, 8)
center_loss_kernel(const float* __restrict__ x,
                   const int*   __restrict__ labels_i32,
                   const float* __restrict__ centers,
                   float*       __restrict__ out) {
    const int tid  = threadIdx.x;
    const int lane = tid & 31;
    const int wid  = tid >> 5;
    const int gt   = blockIdx.x * TPB + tid;

    // ---- barrier-free label-width detection (per-warp ballot, L1-hot) ----
    // int64 LE: odd int32 words of first 16 pairs (labels in [0,751)) are 0.
    int hiw = (lane < 16) ? __ldg(labels_i32 + 2 * lane + 1) : 0;
    const int lblshift = (__ballot_sync(0xFFFFFFFFu, hiw != 0) == 0u) ? 1 : 0;

    const float4* __restrict__ xq = (const float4*)x;
    const float4* __restrict__ cq = (const float4*)centers;

    // Flat streaming accumulate over (row, float4-chunk) space.
    // clamp(d,1e-12,1e12) is inert here (row distances ~4096), so the global
    // sum equals the sum of per-row sums; no per-row reduction needed.
    float acc0 = 0.f, acc1 = 0.f;
    int i = gt;

    #define SLOT(IDX, ACC)                                                    \
        {                                                                     \
            const int   _i   = (IDX);                                         \
            const int   _row = _i >> 9;                                       \
            const int   _lbl = __ldg(labels_i32 + (_row << lblshift));        \
            const float4 _a  = __ldcs(xq + _i);              /* stream x */   \
            const float4 _c  = __ldg(cq + (((size_t)_lbl) << 9) + (_i & 511));\
            float _d;                                                         \
            _d = _a.x - _c.x; ACC += _d * _d;                                 \
            _d = _a.y - _c.y; ACC += _d * _d;                                 \
            _d = _a.z - _c.z; ACC += _d * _d;                                 \
            _d = _a.w - _c.w; ACC += _d * _d;                                 \
        }

    for (; i + NTHREADS < TOTAL4; i += 2 * NTHREADS) {
        SLOT(i,            acc0)
        SLOT(i + NTHREADS, acc1)
    }
    for (; i < TOTAL4; i += NTHREADS)
        SLOT(i, acc0)
    #undef SLOT

    float acc = acc0 + acc1;

    // ---- single end-of-kernel reduction (fixed order -> deterministic) ----
    #pragma unroll
    for (int off = 16; off > 0; off >>= 1)
        acc += __shfl_xor_sync(0xFFFFFFFFu, acc, off);

    __shared__ float s_w[TPB / 32];
    if (lane == 0) s_w[wid] = acc;
    __syncthreads();

    __shared__ bool s_is_last;
    if (tid == 0) {
        float p = 0.0f;
        #pragma unroll
        for (int w = 0; w < TPB / 32; w++) p += s_w[w];
        g_partial[blockIdx.x] = p;
        unsigned int prev;
        // release orders the partial store; acquire makes all partials
        // visible to the last block. No MEMBAR / CCTL.IVALL spam.
        asm volatile("atom.acq_rel.gpu.global.add.u32 %0, [%1], %2;"
                     : "=r"(prev)
                     : "l"(&g_done_count), "r"(1u)
                     : "memory");
        s_is_last = (prev == (unsigned int)(NBLK - 1));
    }
    __syncthreads();

    if (s_is_last) {
        float lacc = 0.0f;
        for (int j = tid; j < NBLK; j += TPB)      // fixed order per thread
            lacc += __ldcg(&g_partial[j]);

        #pragma unroll
        for (int off = 16; off > 0; off >>= 1)
            lacc += __shfl_xor_sync(0xFFFFFFFFu, lacc, off);

        __shared__ float s_fin[TPB / 32];
        if (lane == 0) s_fin[wid] = lacc;
        __syncthreads();

        if (tid == 0) {
            float total = 0.0f;
            #pragma unroll
            for (int w = 0; w < TPB / 32; w++) total += s_fin[w];
            const float clipped_zeros =
                (float)BATCH * (float)(NUM_CLASSES - 1) * 1e-12f;
            out[0] = (total + clipped_zeros) / (float)BATCH;
            g_done_count = 0;                       // reset for graph replay
        }
    }
}

extern "C" void kernel_launch(void* const* d_in, const int* in_sizes, int n_in,
                              void* d_out, int out_size) {
    const float* x       = (const float*)d_in[0];
    const int*   labels  = (const int*)d_in[1];   // width detected in-kernel
    const float* centers = (const float*)d_in[2];
    float*       out     = (float*)d_out;

    center_loss_kernel<<<NBLK, TPB>>>(x, labels, centers, out);
}

// round 8
// speedup vs baseline: 1.0151x; 1.0151x over previous
#include <cuda_runtime.h>
#include <cstdint>

#define BATCH       8192
#define FEAT_DIM    2048
#define NUM_CLASSES 751
#define TPB         256
#define NBLK        592                         // 4 CTAs/SM * 148 SMs, one wave
#define NTHREADS    (NBLK * TPB)                // 151552
#define TOTAL4      (BATCH * (FEAT_DIM / 4))    // 4,194,304 float4 pairs

__device__ float        g_partial[NBLK];
__device__ unsigned int g_done_count;           // zero at load; last block resets

__global__ void __launch_bounds__(TPB, 4)
center_loss_kernel(const float* __restrict__ x,
                   const int*   __restrict__ labels_i32,
                   const float* __restrict__ centers,
                   float*       __restrict__ out) {
    const int tid  = threadIdx.x;
    const int lane = tid & 31;
    const int wid  = tid >> 5;
    const int gt   = blockIdx.x * TPB + tid;

    // ---- barrier-free label-width detection (per-warp ballot, L1-hot) ----
    // int64 LE: odd int32 words of first 16 pairs (labels in [0,751)) are 0.
    int hiw = (lane < 16) ? __ldg(labels_i32 + 2 * lane + 1) : 0;
    const int lblshift = (__ballot_sync(0xFFFFFFFFu, hiw != 0) == 0u) ? 1 : 0;

    const float4* __restrict__ xq = (const float4*)x;
    const float4* __restrict__ cq = (const float4*)centers;

    // Safe (clamped) label fetch for slot index i — never reads OOB, branchless.
    #define LBL_AT(I) __ldg(labels_i32 + \
        ((unsigned)(((I) < TOTAL4 ? (I) : (TOTAL4 - 1)) >> 9) << lblshift))

    // Flat streaming accumulate over (row, float4-chunk) space.
    // clamp(d,1e-12,1e12) is inert here (row distances ~4096), so the global
    // sum equals the sum of per-row sums; no per-row reduction needed.
    float acc0 = 0.f, acc1 = 0.f, acc2 = 0.f, acc3 = 0.f;
    int i = gt;

    // ---- prefetch labels for the first group (software pipeline prologue) --
    int l0 = LBL_AT(i);
    int l1 = LBL_AT(i +     NTHREADS);
    int l2 = LBL_AT(i + 2 * NTHREADS);
    int l3 = LBL_AT(i + 3 * NTHREADS);

    for (; i + 3 * NTHREADS < TOTAL4; ) {
        const int i0 = i, i1 = i + NTHREADS, i2 = i + 2 * NTHREADS, i3 = i + 3 * NTHREADS;

        // x loads (label-independent) — issue immediately
        const float4 a0 = __ldg(xq + i0);
        const float4 a1 = __ldg(xq + i1);
        const float4 a2 = __ldg(xq + i2);
        const float4 a3 = __ldg(xq + i3);

        // c loads — labels were prefetched a full group ago, chain resolved
        const float4 c0 = __ldg(cq + (((size_t)l0) << 9) + (i0 & 511));
        const float4 c1 = __ldg(cq + (((size_t)l1) << 9) + (i1 & 511));
        const float4 c2 = __ldg(cq + (((size_t)l2) << 9) + (i2 & 511));
        const float4 c3 = __ldg(cq + (((size_t)l3) << 9) + (i3 & 511));

        // prefetch next group's labels while the above loads are in flight
        i += 4 * NTHREADS;
        l0 = LBL_AT(i);
        l1 = LBL_AT(i +     NTHREADS);
        l2 = LBL_AT(i + 2 * NTHREADS);
        l3 = LBL_AT(i + 3 * NTHREADS);

        float d;
        d = a0.x - c0.x; acc0 += d * d;  d = a0.y - c0.y; acc0 += d * d;
        d = a0.z - c0.z; acc0 += d * d;  d = a0.w - c0.w; acc0 += d * d;
        d = a1.x - c1.x; acc1 += d * d;  d = a1.y - c1.y; acc1 += d * d;
        d = a1.z - c1.z; acc1 += d * d;  d = a1.w - c1.w; acc1 += d * d;
        d = a2.x - c2.x; acc2 += d * d;  d = a2.y - c2.y; acc2 += d * d;
        d = a2.z - c2.z; acc2 += d * d;  d = a2.w - c2.w; acc2 += d * d;
        d = a3.x - c3.x; acc3 += d * d;  d = a3.y - c3.y; acc3 += d * d;
        d = a3.z - c3.z; acc3 += d * d;  d = a3.w - c3.w; acc3 += d * d;
    }
    // tail: 0-3 remaining slots (labels l0..l2 already prefetched in order)
    for (; i < TOTAL4; i += NTHREADS) {
        const int lbl = LBL_AT(i);
        const float4 a = __ldg(xq + i);
        const float4 c = __ldg(cq + (((size_t)lbl) << 9) + (i & 511));
        float d;
        d = a.x - c.x; acc0 += d * d;  d = a.y - c.y; acc0 += d * d;
        d = a.z - c.z; acc0 += d * d;  d = a.w - c.w; acc0 += d * d;
    }
    #undef LBL_AT

    float acc = (acc0 + acc1) + (acc2 + acc3);

    // ---- single end-of-kernel reduction (fixed order -> deterministic) ----
    #pragma unroll
    for (int off = 16; off > 0; off >>= 1)
        acc += __shfl_xor_sync(0xFFFFFFFFu, acc, off);

    __shared__ float s_w[TPB / 32];
    if (lane == 0) s_w[wid] = acc;
    __syncthreads();

    __shared__ bool s_is_last;
    if (tid == 0) {
        float p = 0.0f;
        #pragma unroll
        for (int w = 0; w < TPB / 32; w++) p += s_w[w];
        g_partial[blockIdx.x] = p;
        unsigned int prev;
        // release orders the partial store; acquire makes all partials
        // visible to the last block. No MEMBAR / CCTL.IVALL spam.
        asm volatile("atom.acq_rel.gpu.global.add.u32 %0, [%1], %2;"
                     : "=r"(prev)
                     : "l"(&g_done_count), "r"(1u)
                     : "memory");
        s_is_last = (prev == (unsigned int)(NBLK - 1));
    }
    __syncthreads();

    if (s_is_last) {
        float lacc = 0.0f;
        for (int j = tid; j < NBLK; j += TPB)      // fixed order per thread
            lacc += __ldcg(&g_partial[j]);

        #pragma unroll
        for (int off = 16; off > 0; off >>= 1)
            lacc += __shfl_xor_sync(0xFFFFFFFFu, lacc, off);

        __shared__ float s_fin[TPB / 32];
        if (lane == 0) s_fin[wid] = lacc;
        __syncthreads();

        if (tid == 0) {
            float total = 0.0f;
            #pragma unroll
            for (int w = 0; w < TPB / 32; w++) total += s_fin[w];
            const float clipped_zeros =
                (float)BATCH * (float)(NUM_CLASSES - 1) * 1e-12f;
            out[0] = (total + clipped_zeros) / (float)BATCH;
            g_done_count = 0;                       // reset for graph replay
        }
    }
}

extern "C" void kernel_launch(void* const* d_in, const int* in_sizes, int n_in,
                              void* d_out, int out_size) {
    const float* x       = (const float*)d_in[0];
    const int*   labels  = (const int*)d_in[1];   // width detected in-kernel
    const float* centers = (const float*)d_in[2];
    float*       out     = (float*)d_out;

    center_loss_kernel<<<NBLK, TPB>>>(x, labels, centers, out);
}

// round 9
// speedup vs baseline: 1.0194x; 1.0043x over previous
#include <cuda_runtime.h>
#include <cstdint>

#define BATCH       8192
#define FEAT_DIM    2048
#define NUM_CLASSES 751
#define TPB         256
#define NBLK        592                          // 4 CTAs/SM * 148 SMs
#define TILE_ROWS   2
#define TILE_F4     (TILE_ROWS * FEAT_DIM / 4)   // 1024 float4 = 16 KB
#define TILE_BYTES  (TILE_F4 * 16)
#define NTILES      (BATCH / TILE_ROWS)          // 4096
#define STAGES      2

__device__ float        g_partial[NBLK];
__device__ unsigned int g_done_count;            // zero at load; last block resets

__device__ __forceinline__ unsigned smem_u32(const void* p) {
    unsigned a;
    asm("{ .reg .u64 t; cvta.to.shared.u64 t, %1; cvt.u32.u64 %0, t; }"
        : "=r"(a) : "l"(p));
    return a;
}

__device__ __forceinline__ void mbar_init(unsigned mbar, unsigned cnt) {
    asm volatile("mbarrier.init.shared.b64 [%0], %1;" :: "r"(mbar), "r"(cnt) : "memory");
}
__device__ __forceinline__ void mbar_expect_tx(unsigned mbar, unsigned bytes) {
    asm volatile("mbarrier.arrive.expect_tx.shared.b64 _, [%0], %1;"
                 :: "r"(mbar), "r"(bytes) : "memory");
}
__device__ __forceinline__ void mbar_wait(unsigned mbar, unsigned phase) {
    asm volatile(
        "{\n\t"
        ".reg .pred P;\n\t"
        "WL_%=:\n\t"
        "mbarrier.try_wait.parity.acquire.cta.shared::cta.b64 P, [%0], %1, 0x989680;\n\t"
        "@P bra.uni WD_%=;\n\t"
        "bra.uni WL_%=;\n\t"
        "WD_%=:\n\t"
        "}" :: "r"(mbar), "r"(phase) : "memory");
}
__device__ __forceinline__ void bulk_copy_g2s(unsigned smem_dst, const void* gmem_src,
                                              unsigned bytes, unsigned mbar) {
    asm volatile(
        "cp.async.bulk.shared::cta.global.mbarrier::complete_tx::bytes [%0], [%1], %2, [%3];"
        :: "r"(smem_dst), "l"(gmem_src), "r"(bytes), "r"(mbar) : "memory");
}
__device__ __forceinline__ void fence_proxy_async_shared() {
    asm volatile("fence.proxy.async.shared::cta;" ::: "memory");
}

__global__ void __launch_bounds__(TPB, 4)
center_loss_kernel(const float* __restrict__ x,
                   const int*   __restrict__ labels_i32,
                   const float* __restrict__ centers,
                   float*       __restrict__ out) {
    __shared__ alignas(128) float4   s_tile[STAGES][TILE_F4];  // 32 KB
    __shared__ alignas(8)   uint64_t s_mbar[STAGES];

    const int tid  = threadIdx.x;
    const int lane = tid & 31;
    const int wid  = tid >> 5;
    // warp -> (row within tile, quarter of the row)
    const int trow = wid >> 2;          // 0 or 1
    const int wq   = wid & 3;           // 0..3
    const int base = wq * 128 + lane;   // float4 index within row (+32k, k<4)

    const unsigned mb0 = smem_u32(&s_mbar[0]);
    const unsigned mb1 = smem_u32(&s_mbar[1]);
    const unsigned st0 = smem_u32(&s_tile[0][0]);
    const unsigned st1 = smem_u32(&s_tile[1][0]);

    // ---- barrier-free label-width detection (per-warp ballot, L1-hot) ----
    // int64 LE: odd int32 words of first 16 pairs (labels in [0,751)) are 0.
    int hiw = (lane < 16) ? __ldg(labels_i32 + 2 * lane + 1) : 0;
    const int lblshift = (__ballot_sync(0xFFFFFFFFu, hiw != 0) == 0u) ? 1 : 0;

    const float4* __restrict__ cq = (const float4*)centers;

    if (tid == 0) {
        mbar_init(mb0, 1);
        mbar_init(mb1, 1);
    }
    __syncthreads();

    const int t0 = blockIdx.x;
    // ---- prologue: fill both stages ----
    if (tid == 0) {
        mbar_expect_tx(mb0, TILE_BYTES);
        bulk_copy_g2s(st0, x + (size_t)t0 * TILE_ROWS * FEAT_DIM, TILE_BYTES, mb0);
        if (t0 + NBLK < NTILES) {
            mbar_expect_tx(mb1, TILE_BYTES);
            bulk_copy_g2s(st1, x + (size_t)(t0 + NBLK) * TILE_ROWS * FEAT_DIM,
                          TILE_BYTES, mb1);
        }
    }

    float acc = 0.0f;
    int ph0 = 0, ph1 = 0;

    // process tile t from stage (s_ptr), then refill that stage with t+2*NBLK
    #define PROCESS(T, STPTR, MB, PH)                                          \
        {                                                                      \
            mbar_wait((MB), (PH)); (PH) ^= 1;                                  \
            const int   _row = (T) * TILE_ROWS + trow;                         \
            const int   _lbl = __ldg(labels_i32 + (_row << lblshift));         \
            const float4* __restrict__ _cr = cq + (((size_t)_lbl) << 9);       \
            const float4* _sx = (const float4*)(STPTR) + trow * (FEAT_DIM/4);  \
            float4 a0 = _sx[base      ];                                       \
            float4 a1 = _sx[base +  32];                                       \
            float4 a2 = _sx[base +  64];                                       \
            float4 a3 = _sx[base +  96];                                       \
            float4 c0 = __ldg(_cr + base      );                               \
            float4 c1 = __ldg(_cr + base +  32);                               \
            float4 c2 = __ldg(_cr + base +  64);                               \
            float4 c3 = __ldg(_cr + base +  96);                               \
            float d;                                                           \
            d = a0.x - c0.x; acc += d * d;  d = a0.y - c0.y; acc += d * d;     \
            d = a0.z - c0.z; acc += d * d;  d = a0.w - c0.w; acc += d * d;     \
            d = a1.x - c1.x; acc += d * d;  d = a1.y - c1.y; acc += d * d;     \
            d = a1.z - c1.z; acc += d * d;  d = a1.w - c1.w; acc += d * d;     \
            d = a2.x - c2.x; acc += d * d;  d = a2.y - c2.y; acc += d * d;     \
            d = a2.z - c2.z; acc += d * d;  d = a2.w - c2.w; acc += d * d;     \
            d = a3.x - c3.x; acc += d * d;  d = a3.y - c3.y; acc += d * d;     \
            d = a3.z - c3.z; acc += d * d;  d = a3.w - c3.w; acc += d * d;     \
            __syncthreads();                /* all lanes done reading stage */ \
            const int _nx = (T) + STAGES * NBLK;                               \
            if (tid == 0 && _nx < NTILES) {                                    \
                fence_proxy_async_shared();  /* order reads before refill */   \
                mbar_expect_tx((MB), TILE_BYTES);                              \
                bulk_copy_g2s(smem_u32(STPTR),                                 \
                              x + (size_t)_nx * TILE_ROWS * FEAT_DIM,          \
                              TILE_BYTES, (MB));                               \
            }                                                                  \
        }

    for (int t = t0; t < NTILES; t += STAGES * NBLK) {
        PROCESS(t, &s_tile[0][0], mb0, ph0)
        if (t + NBLK < NTILES)
            PROCESS(t + NBLK, &s_tile[1][0], mb1, ph1)
    }
    #undef PROCESS

    // ---- single end-of-kernel reduction (fixed order -> deterministic) ----
    // clamp(d,1e-12,1e12) is inert (row distances ~4096), so global sum of
    // squared diffs equals the sum of clamped row sums.
    #pragma unroll
    for (int off = 16; off > 0; off >>= 1)
        acc += __shfl_xor_sync(0xFFFFFFFFu, acc, off);

    __shared__ float s_w[TPB / 32];
    if (lane == 0) s_w[wid] = acc;
    __syncthreads();

    __shared__ bool s_is_last;
    if (tid == 0) {
        float p = 0.0f;
        #pragma unroll
        for (int w = 0; w < TPB / 32; w++) p += s_w[w];
        g_partial[blockIdx.x] = p;
        unsigned int prev;
        asm volatile("atom.acq_rel.gpu.global.add.u32 %0, [%1], %2;"
                     : "=r"(prev)
                     : "l"(&g_done_count), "r"(1u)
                     : "memory");
        s_is_last = (prev == (unsigned int)(NBLK - 1));
    }
    __syncthreads();

    if (s_is_last) {
        float lacc = 0.0f;
        for (int j = tid; j < NBLK; j += TPB)       // fixed order per thread
            lacc += __ldcg(&g_partial[j]);

        #pragma unroll
        for (int off = 16; off > 0; off >>= 1)
            lacc += __shfl_xor_sync(0xFFFFFFFFu, lacc, off);

        __shared__ float s_fin[TPB / 32];
        if (lane == 0) s_fin[wid] = lacc;
        __syncthreads();

        if (tid == 0) {
            float total = 0.0f;
            #pragma unroll
            for (int w = 0; w < TPB / 32; w++) total += s_fin[w];
            const float clipped_zeros =
                (float)BATCH * (float)(NUM_CLASSES - 1) * 1e-12f;
            out[0] = (total + clipped_zeros) / (float)BATCH;
            g_done_count = 0;                        // reset for graph replay
        }
    }
}

extern "C" void kernel_launch(void* const* d_in, const int* in_sizes, int n_in,
                              void* d_out, int out_size) {
    const float* x       = (const float*)d_in[0];
    const int*   labels  = (const int*)d_in[1];   // width detected in-kernel
    const float* centers = (const float*)d_in[2];
    float*       out     = (float*)d_out;

    center_loss_kernel<<<NBLK, TPB>>>(x, labels, centers, out);
}